// round 1
// baseline (speedup 1.0000x reference)
#include <cuda_runtime.h>

// TropicalLeNet, fully fused: one CTA per batch image.
//   conv1: min-plus, C=1 -> O=6, k=5, pad=2, fused with 2x2 avgpool -> p1[6][14][14]
//   conv2: max-plus, C=6 -> O=16, k=5, pad=0, fused with 2x2 avgpool -> p2[400]
//   fc1 400->120 relu, fc2 120->84 relu, fc3 84->10
// All intermediates in shared memory; weights for convs cached in smem,
// FC weights streamed from global (L2-resident across the 256 CTAs).

__global__ void __launch_bounds__(256)
lenet_fused_kernel(const float* __restrict__ input,
                   const float* __restrict__ w1,
                   const float* __restrict__ w2,
                   const float* __restrict__ fw1,
                   const float* __restrict__ fb1,
                   const float* __restrict__ fw2,
                   const float* __restrict__ fb2,
                   const float* __restrict__ fw3,
                   const float* __restrict__ fb3,
                   float* __restrict__ out)
{
    const int b   = blockIdx.x;
    const int tid = threadIdx.x;

    __shared__ float xp[32 * 33];      // zero-padded 32x32 input, row stride 33
    __shared__ float w1s[6 * 25];
    __shared__ float w2s[16 * 6 * 25];
    __shared__ float p1[6 * 14 * 14];  // conv1+pool output
    __shared__ float p2[400];          // conv2+pool output (flatten order o*25+i*5+j)
    __shared__ float h1[120];
    __shared__ float h2[84];

    // ---- stage 0: load input (zero-padded) and conv weights into smem ----
    for (int i = tid; i < 32 * 33; i += 256) xp[i] = 0.0f;
    for (int i = tid; i < 150;     i += 256) w1s[i] = w1[i];
    for (int i = tid; i < 2400;    i += 256) w2s[i] = w2[i];
    __syncthreads();

    const float* inb = input + b * 784;
    for (int i = tid; i < 784; i += 256) {
        int h = i / 28, w = i % 28;
        xp[(h + 2) * 33 + (w + 2)] = inb[i];
    }
    __syncthreads();

    // ---- stage 1: min-plus conv1 fused with avgpool2 -> p1[6][14][14] ----
    // p1[c,i,j] = 0.25 * sum_{u,v in 2x2} min_{5x5 taps}(xp + w1)
    for (int e = tid; e < 6 * 14 * 14; e += 256) {
        int c = e / 196, r = e % 196;
        int i = r / 14, j = r % 14;

        float wr[25];
        #pragma unroll
        for (int t = 0; t < 25; t++) wr[t] = w1s[c * 25 + t];

        float win[6][6];
        #pragma unroll
        for (int u = 0; u < 6; u++)
            #pragma unroll
            for (int v = 0; v < 6; v++)
                win[u][v] = xp[(2 * i + u) * 33 + (2 * j + v)];

        float acc = 0.0f;
        #pragma unroll
        for (int u = 0; u < 2; u++)
        #pragma unroll
        for (int v = 0; v < 2; v++) {
            float m = __int_as_float(0x7f800000);  // +inf
            #pragma unroll
            for (int di = 0; di < 5; di++)
                #pragma unroll
                for (int dj = 0; dj < 5; dj++)
                    m = fminf(m, win[u + di][v + dj] + wr[di * 5 + dj]);
            acc += m;
        }
        p1[e] = 0.25f * acc;
    }
    __syncthreads();

    // ---- stage 2: max-plus conv2 fused with avgpool2 -> p2[400] ----
    // p2[o*25+i*5+j] = 0.25 * sum_c sum_{u,v in 2x2} max_{5x5 taps}(p1 + w2)
    for (int e = tid; e < 400; e += 256) {
        int o = e / 25, r = e % 25;
        int i = r / 5, j = r % 5;

        float acc = 0.0f;
        #pragma unroll 1
        for (int c = 0; c < 6; c++) {
            float wr[25];
            #pragma unroll
            for (int t = 0; t < 25; t++) wr[t] = w2s[(o * 6 + c) * 25 + t];

            float win[6][6];
            #pragma unroll
            for (int u = 0; u < 6; u++)
                #pragma unroll
                for (int v = 0; v < 6; v++)
                    win[u][v] = p1[c * 196 + (2 * i + u) * 14 + (2 * j + v)];

            #pragma unroll
            for (int u = 0; u < 2; u++)
            #pragma unroll
            for (int v = 0; v < 2; v++) {
                float m = __int_as_float(0xff800000);  // -inf
                #pragma unroll
                for (int di = 0; di < 5; di++)
                    #pragma unroll
                    for (int dj = 0; dj < 5; dj++)
                        m = fmaxf(m, win[u + di][v + dj] + wr[di * 5 + dj]);
                acc += m;
            }
        }
        p2[e] = 0.25f * acc;
    }
    __syncthreads();

    // ---- stage 3: FC layers, warp-per-output ----
    const int warp = tid >> 5;
    const int lane = tid & 31;

    // fc1: 400 -> 120, relu
    for (int o = warp; o < 120; o += 8) {
        const float* wrow = fw1 + o * 400;
        float s = 0.0f;
        for (int i = lane; i < 400; i += 32) s += p2[i] * wrow[i];
        #pragma unroll
        for (int off = 16; off; off >>= 1) s += __shfl_xor_sync(0xffffffffu, s, off);
        if (lane == 0) h1[o] = fmaxf(s + fb1[o], 0.0f);
    }
    __syncthreads();

    // fc2: 120 -> 84, relu
    for (int o = warp; o < 84; o += 8) {
        const float* wrow = fw2 + o * 120;
        float s = 0.0f;
        for (int i = lane; i < 120; i += 32) s += h1[i] * wrow[i];
        #pragma unroll
        for (int off = 16; off; off >>= 1) s += __shfl_xor_sync(0xffffffffu, s, off);
        if (lane == 0) h2[o] = fmaxf(s + fb2[o], 0.0f);
    }
    __syncthreads();

    // fc3: 84 -> 10
    for (int o = warp; o < 10; o += 8) {
        const float* wrow = fw3 + o * 84;
        float s = 0.0f;
        for (int i = lane; i < 84; i += 32) s += h2[i] * wrow[i];
        #pragma unroll
        for (int off = 16; off; off >>= 1) s += __shfl_xor_sync(0xffffffffu, s, off);
        if (lane == 0) out[b * 10 + o] = s + fb3[o];
    }
}

extern "C" void kernel_launch(void* const* d_in, const int* in_sizes, int n_in,
                              void* d_out, int out_size)
{
    const float* input = (const float*)d_in[0];
    const float* w1    = (const float*)d_in[1];
    const float* w2    = (const float*)d_in[2];
    const float* fw1   = (const float*)d_in[3];
    const float* fb1   = (const float*)d_in[4];
    const float* fw2   = (const float*)d_in[5];
    const float* fb2   = (const float*)d_in[6];
    const float* fw3   = (const float*)d_in[7];
    const float* fb3   = (const float*)d_in[8];

    const int B = in_sizes[0] / 784;  // 256

    lenet_fused_kernel<<<B, 256>>>(input, w1, w2, fw1, fb1, fw2, fb2, fw3, fb3,
                                   (float*)d_out);
}

// round 2
// speedup vs baseline: 1.7286x; 1.7286x over previous
#include <cuda_runtime.h>

// TropicalLeNet split into 3 stage-matched kernels.
// Intermediates in __device__ global scratch (L2-resident between launches).

#define BMAX 256

__device__ float g_p1[BMAX * 6 * 14 * 14];  // conv1+pool output
__device__ float g_p2[BMAX * 400];          // conv2+pool output (flatten o*25+i*5+j)

// ---------------------------------------------------------------------------
// Kernel A: min-plus conv1 (C=1 -> O=6, k=5, pad=2) fused with 2x2 avgpool.
// grid (6, B): one CTA per (out-channel, image). 224 threads, 196 active.
// ---------------------------------------------------------------------------
__global__ void __launch_bounds__(224)
conv1_kernel(const float* __restrict__ input, const float* __restrict__ w1)
{
    const int c = blockIdx.x, b = blockIdx.y;
    const int tid = threadIdx.x;

    __shared__ float xp[32 * 33];   // zero-padded input, row stride 33
    __shared__ float ws[25];

    for (int i = tid; i < 32 * 33; i += 224) xp[i] = 0.0f;
    if (tid < 25) ws[tid] = w1[c * 25 + tid];
    __syncthreads();

    const float* inb = input + b * 784;
    for (int i = tid; i < 784; i += 224) {
        int h = i / 28, w = i % 28;
        xp[(h + 2) * 33 + (w + 2)] = inb[i];
    }
    __syncthreads();

    if (tid < 196) {
        const int i = tid / 14, j = tid % 14;

        float wr[25];
        #pragma unroll
        for (int t = 0; t < 25; t++) wr[t] = ws[t];   // warp-uniform broadcast

        float win[6][6];
        #pragma unroll
        for (int u = 0; u < 6; u++)
            #pragma unroll
            for (int v = 0; v < 6; v++)
                win[u][v] = xp[(2 * i + u) * 33 + (2 * j + v)];

        float acc = 0.0f;
        #pragma unroll
        for (int u = 0; u < 2; u++)
        #pragma unroll
        for (int v = 0; v < 2; v++) {
            float m = win[u][v] + wr[0];
            #pragma unroll
            for (int t = 1; t < 25; t++)
                m = fminf(m, win[u + t / 5][v + t % 5] + wr[t]);
            acc += m;
        }
        g_p1[(b * 6 + c) * 196 + tid] = 0.25f * acc;
    }
}

// ---------------------------------------------------------------------------
// Kernel B: max-plus conv2 (C=6 -> O=16, k=5, pad=0) fused with 2x2 avgpool.
// grid (4, B): one CTA per (4-channel output group, image). 128 threads:
// warp w owns output channel og*4+w; lanes 0..24 compute the 25 spatial outs.
// ---------------------------------------------------------------------------
__global__ void __launch_bounds__(128)
conv2_kernel(const float* __restrict__ w2)
{
    const int og = blockIdx.x, b = blockIdx.y;
    const int tid = threadIdx.x;

    __shared__ float p1s[6 * 14 * 14];  // 1176
    __shared__ float ws[4 * 6 * 25];    // 600

    const float* p1b = g_p1 + b * 1176;
    for (int i = tid; i < 1176; i += 128) p1s[i] = p1b[i];
    for (int i = tid; i < 600;  i += 128) ws[i]  = w2[og * 600 + i];
    __syncthreads();

    const int ol   = tid >> 5;          // warp id = local output channel
    const int lane = tid & 31;
    if (lane < 25) {
        const int i = lane / 5, j = lane % 5;

        float acc = 0.0f;
        #pragma unroll
        for (int c = 0; c < 6; c++) {
            float win[6][6];
            #pragma unroll
            for (int u = 0; u < 6; u++)
                #pragma unroll
                for (int v = 0; v < 6; v++)
                    win[u][v] = p1s[c * 196 + (2 * i + u) * 14 + (2 * j + v)];

            const float* wr = &ws[ol * 150 + c * 25];  // warp-uniform broadcast

            #pragma unroll
            for (int u = 0; u < 2; u++)
            #pragma unroll
            for (int v = 0; v < 2; v++) {
                float m = win[u][v] + wr[0];
                #pragma unroll
                for (int t = 1; t < 25; t++)
                    m = fmaxf(m, win[u + t / 5][v + t % 5] + wr[t]);
                acc += m;
            }
        }
        g_p2[b * 400 + (og * 4 + ol) * 25 + lane] = 0.25f * acc;
    }
}

// ---------------------------------------------------------------------------
// Kernel C: FC stack. grid B, 256 threads. Warp computes 2 outputs per pass
// (shared x loads, doubled accumulator ILP).
// ---------------------------------------------------------------------------
__global__ void __launch_bounds__(256)
fc_kernel(const float* __restrict__ fw1, const float* __restrict__ fb1,
          const float* __restrict__ fw2, const float* __restrict__ fb2,
          const float* __restrict__ fw3, const float* __restrict__ fb3,
          float* __restrict__ out)
{
    const int b = blockIdx.x;
    const int tid = threadIdx.x;
    const int warp = tid >> 5, lane = tid & 31;

    __shared__ float x[400];
    __shared__ float h1[120];
    __shared__ float h2[84];

    for (int i = tid; i < 400; i += 256) x[i] = g_p2[b * 400 + i];
    __syncthreads();

    // fc1: 400 -> 120, relu. 60 output-pairs over 8 warps.
    for (int oo = warp; oo < 60; oo += 8) {
        const int o0 = 2 * oo, o1 = 2 * oo + 1;
        const float* wa = fw1 + o0 * 400;
        const float* wb = fw1 + o1 * 400;
        float sa = 0.0f, sb = 0.0f;
        #pragma unroll 4
        for (int i = lane; i < 400; i += 32) {
            float xv = x[i];
            sa += xv * wa[i];
            sb += xv * wb[i];
        }
        #pragma unroll
        for (int off = 16; off; off >>= 1) {
            sa += __shfl_xor_sync(0xffffffffu, sa, off);
            sb += __shfl_xor_sync(0xffffffffu, sb, off);
        }
        if (lane == 0) {
            h1[o0] = fmaxf(sa + fb1[o0], 0.0f);
            h1[o1] = fmaxf(sb + fb1[o1], 0.0f);
        }
    }
    __syncthreads();

    // fc2: 120 -> 84, relu. 42 output-pairs over 8 warps.
    for (int oo = warp; oo < 42; oo += 8) {
        const int o0 = 2 * oo, o1 = 2 * oo + 1;
        const float* wa = fw2 + o0 * 120;
        const float* wb = fw2 + o1 * 120;
        float sa = 0.0f, sb = 0.0f;
        #pragma unroll
        for (int i = lane; i < 120; i += 32) {
            float xv = h1[i];
            sa += xv * wa[i];
            sb += xv * wb[i];
        }
        #pragma unroll
        for (int off = 16; off; off >>= 1) {
            sa += __shfl_xor_sync(0xffffffffu, sa, off);
            sb += __shfl_xor_sync(0xffffffffu, sb, off);
        }
        if (lane == 0) {
            h2[o0] = fmaxf(sa + fb2[o0], 0.0f);
            h2[o1] = fmaxf(sb + fb2[o1], 0.0f);
        }
    }
    __syncthreads();

    // fc3: 84 -> 10.
    for (int o = warp; o < 10; o += 8) {
        const float* wrow = fw3 + o * 84;
        float s = 0.0f;
        #pragma unroll
        for (int i = lane; i < 84; i += 32) s += h2[i] * wrow[i];
        #pragma unroll
        for (int off = 16; off; off >>= 1) s += __shfl_xor_sync(0xffffffffu, s, off);
        if (lane == 0) out[b * 10 + o] = s + fb3[o];
    }
}

extern "C" void kernel_launch(void* const* d_in, const int* in_sizes, int n_in,
                              void* d_out, int out_size)
{
    const float* input = (const float*)d_in[0];
    const float* w1    = (const float*)d_in[1];
    const float* w2    = (const float*)d_in[2];
    const float* fw1   = (const float*)d_in[3];
    const float* fb1   = (const float*)d_in[4];
    const float* fw2   = (const float*)d_in[5];
    const float* fb2   = (const float*)d_in[6];
    const float* fw3   = (const float*)d_in[7];
    const float* fb3   = (const float*)d_in[8];

    const int B = in_sizes[0] / 784;  // 256

    conv1_kernel<<<dim3(6, B), 224>>>(input, w1);
    conv2_kernel<<<dim3(4, B), 128>>>(w2);
    fc_kernel<<<B, 256>>>(fw1, fb1, fw2, fb2, fw3, fb3, (float*)d_out);
}